// round 8
// baseline (speedup 1.0000x reference)
#include <cuda_runtime.h>
#include <cuda_fp16.h>
#include <math.h>
#include <stdint.h>

// ---------------------------------------------------------------------------
// ArcMarginProduct constants (S=30, M=0.5)
// ---------------------------------------------------------------------------
#define S_SCALE   30.0f
#define INV_S     (1.0f / 30.0f)
#define COS_M_C   0.87758256189037271612f   // cos(0.5)
#define SIN_M_C   0.47942553860420300027f   // sin(0.5)
#define TH_C     (-0.87758256189037271612f) // cos(pi - 0.5)
#define MM_C      7.19138307906304500405f   // S * sin(0.5) * 0.5

#define MAXB  1024
#define CPAD  100096     // 391 * 256; pad rows stay zero (zero-init statics)
#define DFIX  512
#define NYMAX 1024       // >= 782 y-tiles

// fp16, normalization-folded operands
__device__ __align__(256) __half g_Ah[MAXB * DFIX];   // S * a / ||a||
__device__ __align__(256) __half g_Wh[CPAD * DFIX];   // w / ||w||  (filled by GEMM producers)
__device__ int g_flags[NYMAX];                        // per-y-tile ready flags

// ---------------------------------------------------------------------------
// Reset per-launch flags (keeps graph replays deterministic).
// ---------------------------------------------------------------------------
__global__ void reset_flags_kernel(int n)
{
    int i = blockIdx.x * blockDim.x + threadIdx.x;
    if (i < n) g_flags[i] = 0;
}

// ---------------------------------------------------------------------------
// A prologue: per-row L2 norm -> scale by S -> fp16 convert -> scratch.
// ---------------------------------------------------------------------------
__global__ void norm_conv_kernel(const float* __restrict__ x,
                                 __half* __restrict__ dst,
                                 float smul, int D)
{
    int row = blockIdx.x;
    const float4* xv = reinterpret_cast<const float4*>(x + (size_t)row * (size_t)D);
    float4 v = xv[threadIdx.x];

    float s = v.x * v.x + v.y * v.y + v.z * v.z + v.w * v.w;
    #pragma unroll
    for (int off = 16; off > 0; off >>= 1)
        s += __shfl_down_sync(0xffffffffu, s, off);

    __shared__ float wsum[4];
    __shared__ float s_sc;
    int lane = threadIdx.x & 31, wid = threadIdx.x >> 5;
    if (lane == 0) wsum[wid] = s;
    __syncthreads();
    if (threadIdx.x == 0) {
        float t = wsum[0] + wsum[1] + wsum[2] + wsum[3];
        s_sc = smul / fmaxf(sqrtf(t), 1e-12f);
    }
    __syncthreads();
    float sc = s_sc;

    __half2 h01 = __floats2half2_rn(v.x * sc, v.y * sc);
    __half2 h23 = __floats2half2_rn(v.z * sc, v.w * sc);
    __half2* p = reinterpret_cast<__half2*>(dst + (size_t)row * (size_t)D) + threadIdx.x * 2;
    p[0] = h01;
    p[1] = h23;
}

// ---------------------------------------------------------------------------
// fp16 tensor-core GEMM with fused W-conversion producers:
//   CTA x==0 of each y-group converts W rows [y*BN, y*BN+BN) (norm folded),
//   sets a release flag; x>0 CTAs acquire-spin. GEMM body = round-6 config:
//   CTA 128x128, BK=64, 8 warps (2m x 4n), warp tile 64x32, 2 CTAs/SM,
//   SW128 XOR swizzle + ldmatrix, 3-stage cp.async pipeline.
// ---------------------------------------------------------------------------
#define BM 128
#define BN 128
#define BK 64
#define NTHREADS 256
#define A_TILE_BYTES (BM * 128)                      // 16384
#define B_TILE_BYTES (BN * 128)                      // 16384
#define STAGE_BYTES  (A_TILE_BYTES + B_TILE_BYTES)   // 32768
#define NSTAGE 3
#define SMEM_BYTES (NSTAGE * STAGE_BYTES)            // 98304

__device__ __forceinline__ void mma_f16(float* d, const uint32_t* a,
                                        uint32_t b0, uint32_t b1) {
    asm volatile(
        "mma.sync.aligned.m16n8k16.row.col.f32.f16.f16.f32 "
        "{%0,%1,%2,%3}, {%4,%5,%6,%7}, {%8,%9}, {%0,%1,%2,%3};"
        : "+f"(d[0]), "+f"(d[1]), "+f"(d[2]), "+f"(d[3])
        : "r"(a[0]), "r"(a[1]), "r"(a[2]), "r"(a[3]), "r"(b0), "r"(b1));
}

#define LDMATRIX_X4(r0, r1, r2, r3, addr)                                   \
    asm volatile("ldmatrix.sync.aligned.m8n8.x4.shared.b16 "                \
                 "{%0,%1,%2,%3}, [%4];"                                     \
                 : "=r"(r0), "=r"(r1), "=r"(r2), "=r"(r3) : "r"(addr))

__device__ __forceinline__ void cp_async16(uint32_t sm_dst, const void* g_src) {
    asm volatile("cp.async.cg.shared.global [%0], [%1], 16;"
                 :: "r"(sm_dst), "l"(g_src));
}

__global__ void __launch_bounds__(NTHREADS, 2)
arc_gemm_f16(const float* __restrict__ W, float* __restrict__ out, int C, int D)
{
    extern __shared__ char sm[];
    const uint32_t smaddr = (uint32_t)__cvta_generic_to_shared(sm);

    const int tid  = threadIdx.x;
    const int lane = tid & 31;
    const int warp = tid >> 5;
    const int y    = blockIdx.y;
    const int b0   = blockIdx.x * BM;
    const int c0   = y * BN;

    // ---- producer / consumer handshake on W tile readiness ----
    if (blockIdx.x == 0) {
        // Convert W rows [c0, c0+BN): per-warp rows, norm+convert fused.
        for (int rr = warp; rr < BN; rr += 8) {
            int row = c0 + rr;
            if (row < C) {
                const float4* src =
                    reinterpret_cast<const float4*>(W + (size_t)row * (size_t)D) + lane * 4;
                float4 v0 = src[0], v1 = src[1], v2 = src[2], v3 = src[3];
                float s = v0.x*v0.x + v0.y*v0.y + v0.z*v0.z + v0.w*v0.w
                        + v1.x*v1.x + v1.y*v1.y + v1.z*v1.z + v1.w*v1.w
                        + v2.x*v2.x + v2.y*v2.y + v2.z*v2.z + v2.w*v2.w
                        + v3.x*v3.x + v3.y*v3.y + v3.z*v3.z + v3.w*v3.w;
                #pragma unroll
                for (int off = 16; off > 0; off >>= 1)
                    s += __shfl_xor_sync(0xffffffffu, s, off);
                float rn = 1.0f / fmaxf(sqrtf(s), 1e-12f);

                __half2 h[8];
                h[0] = __floats2half2_rn(v0.x*rn, v0.y*rn);
                h[1] = __floats2half2_rn(v0.z*rn, v0.w*rn);
                h[2] = __floats2half2_rn(v1.x*rn, v1.y*rn);
                h[3] = __floats2half2_rn(v1.z*rn, v1.w*rn);
                h[4] = __floats2half2_rn(v2.x*rn, v2.y*rn);
                h[5] = __floats2half2_rn(v2.z*rn, v2.w*rn);
                h[6] = __floats2half2_rn(v3.x*rn, v3.y*rn);
                h[7] = __floats2half2_rn(v3.z*rn, v3.w*rn);
                uint4* dst = reinterpret_cast<uint4*>(
                    g_Wh + (size_t)row * (size_t)D + lane * 16);
                dst[0] = *reinterpret_cast<uint4*>(&h[0]);
                dst[1] = *reinterpret_cast<uint4*>(&h[4]);
            }
        }
        __syncthreads();
        if (tid == 0) {
            int one = 1;
            asm volatile("st.release.gpu.global.u32 [%0], %1;"
                         :: "l"(&g_flags[y]), "r"(one) : "memory");
        }
    } else {
        if (tid == 0) {
            int v = 0;
            do {
                asm volatile("ld.acquire.gpu.global.u32 %0, [%1];"
                             : "=r"(v) : "l"(&g_flags[y]) : "memory");
                if (!v) __nanosleep(64);
            } while (!v);
        }
        __syncthreads();
    }

    // ---- GEMM body (round-6 config) ----
    const int wm = (warp >> 2) * 64;   // 0, 64
    const int wn = (warp & 3) * 32;    // 0, 32, 64, 96
    const int r = lane >> 2;           // 0..7
    const int c = lane & 3;            // 0..3

    float acc[4][4][4];
    #pragma unroll
    for (int mi = 0; mi < 4; mi++)
        #pragma unroll
        for (int ni = 0; ni < 4; ni++)
            #pragma unroll
            for (int j = 0; j < 4; j++)
                acc[mi][ni][j] = 0.0f;

    const int nch = D / BK;   // 8
    const size_t rbytes = (size_t)D * 2;

    const int lane15 = lane & 15;
    const uint32_t kq16 = ((lane >> 4) & 1) << 4;
    const uint32_t sw = (uint32_t)(lane15 & 7) << 4;
    uint32_t relA[4], relB[2];
    #pragma unroll
    for (int t = 0; t < 4; t++)
        relA[t] = (uint32_t)(wm + t * 16 + lane15) * 128;
    #pragma unroll
    for (int t = 0; t < 2; t++)
        relB[t] = A_TILE_BYTES + (uint32_t)(wn + t * 16 + lane15) * 128;

    auto load_chunk = [&](int ch, int st) {
        uint32_t stage = smaddr + st * STAGE_BYTES;
        size_t koff = (size_t)ch * 128;
        #pragma unroll
        for (int h = 0; h < 8; h++) {
            int id = h * NTHREADS + tid;
            int row;
            uint32_t base;
            const char* gsrc;
            if (h < 4) {
                row = id >> 3;
                base = stage;
                gsrc = (const char*)g_Ah + (size_t)(b0 + row) * rbytes + koff;
            } else {
                int id2 = id - 1024;
                row = id2 >> 3;
                base = stage + A_TILE_BYTES;
                gsrc = (const char*)g_Wh + (size_t)(c0 + row) * rbytes + koff;
            }
            int seg = id & 7;
            uint32_t off = (uint32_t)row * 128 +
                           (((uint32_t)seg << 4) ^ (((uint32_t)row & 7) << 4));
            cp_async16(base + off, gsrc + seg * 16);
        }
        asm volatile("cp.async.commit_group;" ::: "memory");
    };

    load_chunk(0, 0);
    load_chunk(1, 1);

    for (int i = 0; i < nch; i++) {
        if (i + 1 < nch)
            asm volatile("cp.async.wait_group 1;" ::: "memory");
        else
            asm volatile("cp.async.wait_group 0;" ::: "memory");
        __syncthreads();

        if (i + 2 < nch)
            load_chunk(i + 2, (i + 2) % NSTAGE);

        uint32_t stage = smaddr + (i % NSTAGE) * STAGE_BYTES;

        #pragma unroll
        for (int ks = 0; ks < 4; ks++) {
            uint32_t kb = ((uint32_t)ks << 5) + kq16;
            uint32_t kx = kb ^ sw;

            uint32_t af[4][4];
            #pragma unroll
            for (int mt = 0; mt < 4; mt++)
                LDMATRIX_X4(af[mt][0], af[mt][1], af[mt][2], af[mt][3],
                            stage + relA[mt] + kx);

            uint32_t bf[2][4];
            #pragma unroll
            for (int nt = 0; nt < 2; nt++)
                LDMATRIX_X4(bf[nt][0], bf[nt][1], bf[nt][2], bf[nt][3],
                            stage + relB[nt] + kx);

            #pragma unroll
            for (int mt = 0; mt < 4; mt++)
                #pragma unroll
                for (int nt = 0; nt < 2; nt++) {
                    mma_f16(acc[mt][nt * 2 + 0], af[mt], bf[nt][0], bf[nt][2]);
                    mma_f16(acc[mt][nt * 2 + 1], af[mt], bf[nt][1], bf[nt][3]);
                }
        }
        __syncthreads();
    }

    // epilogue: bare stores (all scaling folded into operands)
    #pragma unroll
    for (int ni = 0; ni < 4; ni++) {
        int cc = c0 + wn + ni * 8 + 2 * c;
        if (cc < C) {
            #pragma unroll
            for (int mi = 0; mi < 4; mi++) {
                #pragma unroll
                for (int h = 0; h < 2; h++) {
                    int row = b0 + wm + mi * 16 + h * 8 + r;
                    float2 v = make_float2(acc[mi][ni][h * 2 + 0],
                                           acc[mi][ni][h * 2 + 1]);
                    *reinterpret_cast<float2*>(out + (size_t)row * (size_t)C + cc) = v;
                }
            }
        }
    }
}

// ---------------------------------------------------------------------------
// Fixup: margin at label columns only.
// ---------------------------------------------------------------------------
__global__ void fixup_kernel(const int* __restrict__ label, float* __restrict__ out,
                             int B, int C)
{
    int b = blockIdx.x * blockDim.x + threadIdx.x;
    if (b >= B) return;
    int c = label[b];
    if (c < 0 || c >= C) return;
    size_t idx = (size_t)b * (size_t)C + (size_t)c;
    float cosv = out[idx] * INV_S;
    float s2 = 1.0f - cosv * cosv;
    s2 = fminf(fmaxf(s2, 0.0f), 1.0f);
    float sine = sqrtf(s2);
    float phi = cosv * COS_M_C - sine * SIN_M_C;
    phi = (cosv > TH_C) ? phi : (cosv - MM_C);
    out[idx] = phi * S_SCALE;
}

// ---------------------------------------------------------------------------
// Launch
// ---------------------------------------------------------------------------
extern "C" void kernel_launch(void* const* d_in, const int* in_sizes, int n_in,
                              void* d_out, int out_size)
{
    const float* input  = (const float*)d_in[0];   // [B, D]
    const int*   label  = (const int*)  d_in[1];   // [B]
    const float* weight = (const float*)d_in[2];   // [C, D]
    float* out = (float*)d_out;                    // [B, C]

    const int B = in_sizes[1];
    const int D = in_sizes[0] / B;
    const int C = in_sizes[2] / D;
    const int ny = (C + BN - 1) / BN;

    cudaFuncSetAttribute(arc_gemm_f16, cudaFuncAttributeMaxDynamicSharedMemorySize,
                         SMEM_BYTES);

    __half* Ah;  cudaGetSymbolAddress((void**)&Ah, g_Ah);

    // 0) reset producer flags (deterministic across graph replays)
    reset_flags_kernel<<<(ny + 255) / 256, 256>>>(ny);

    // 1) A prologue: normalize + fp16 convert (S folded in)
    norm_conv_kernel<<<B, 128>>>(input, Ah, S_SCALE, D);

    // 2) GEMM with fused W conversion (producer x==0 per y-group)
    dim3 grid(B / BM, ny);
    arc_gemm_f16<<<grid, NTHREADS, SMEM_BYTES>>>(weight, out, C, D);

    // 3) margin fixup at label columns
    fixup_kernel<<<(B + 127) / 128, 128>>>(label, out, B, C);
}

// round 9
// speedup vs baseline: 1.6366x; 1.6366x over previous
#include <cuda_runtime.h>
#include <cuda_fp16.h>
#include <math.h>
#include <stdint.h>

// ---------------------------------------------------------------------------
// ArcMarginProduct constants (S=30, M=0.5)
// ---------------------------------------------------------------------------
#define S_SCALE   30.0f
#define INV_S     (1.0f / 30.0f)
#define COS_M_C   0.87758256189037271612f   // cos(0.5)
#define SIN_M_C   0.47942553860420300027f   // sin(0.5)
#define TH_C     (-0.87758256189037271612f) // cos(pi - 0.5)
#define MM_C      7.19138307906304500405f   // S * sin(0.5) * 0.5

#define MAXB  1024
#define CPAD  100096     // 391 * 256; pad rows stay zero (zero-init statics)
#define DFIX  512
#define NYMAX 1024
#define LOOKAHEAD 64     // groups; > max groups resident per wave (37)

// fp16, normalization-folded operands
__device__ __align__(256) __half g_Ah[MAXB * DFIX];   // S * a / ||a||
__device__ __align__(256) __half g_Wh[CPAD * DFIX];   // w / ||w||
__device__ unsigned g_cnt[NYMAX];                     // per-group arrive counters

// ---------------------------------------------------------------------------
// Reset per-launch counters (deterministic graph replays).
// ---------------------------------------------------------------------------
__global__ void reset_flags_kernel(int n)
{
    int i = blockIdx.x * blockDim.x + threadIdx.x;
    if (i < n) g_cnt[i] = 0u;
}

// ---------------------------------------------------------------------------
// Prologue: per-row L2 norm -> scale -> fp16 convert -> scratch.
// Used for all of A and for the first LOOKAHEAD*BN rows of W.
// ---------------------------------------------------------------------------
__global__ void norm_conv_kernel(const float* __restrict__ x,
                                 __half* __restrict__ dst,
                                 float smul, int D)
{
    int row = blockIdx.x;
    const float4* xv = reinterpret_cast<const float4*>(x + (size_t)row * (size_t)D);
    float4 v = xv[threadIdx.x];

    float s = v.x * v.x + v.y * v.y + v.z * v.z + v.w * v.w;
    #pragma unroll
    for (int off = 16; off > 0; off >>= 1)
        s += __shfl_down_sync(0xffffffffu, s, off);

    __shared__ float wsum[4];
    __shared__ float s_sc;
    int lane = threadIdx.x & 31, wid = threadIdx.x >> 5;
    if (lane == 0) wsum[wid] = s;
    __syncthreads();
    if (threadIdx.x == 0) {
        float t = wsum[0] + wsum[1] + wsum[2] + wsum[3];
        s_sc = smul / fmaxf(sqrtf(t), 1e-12f);
    }
    __syncthreads();
    float sc = s_sc;

    __half2 h01 = __floats2half2_rn(v.x * sc, v.y * sc);
    __half2 h23 = __floats2half2_rn(v.z * sc, v.w * sc);
    __half2* p = reinterpret_cast<__half2*>(dst + (size_t)row * (size_t)D) + threadIdx.x * 2;
    p[0] = h01;
    p[1] = h23;
}

// ---------------------------------------------------------------------------
// fp16 tensor-core GEMM (round-6 config) + look-ahead W conversion:
//   Each CTA of group y converts 16 W rows of group y+LOOKAHEAD (distributed
//   over the group's 8 CTAs), release-arrives on g_cnt[y+LOOKAHEAD], then
//   acquire-spins on g_cnt[y]==8 (skipped for y<LOOKAHEAD; those groups are
//   converted upfront). Converters never wait -> deadlock-free.
// GEMM: CTA 128x128, BK=64, 8 warps (2m x 4n), warp tile 64x32, 2 CTAs/SM,
//   SW128 XOR swizzle + ldmatrix, 3-stage cp.async pipeline.
// ---------------------------------------------------------------------------
#define BM 128
#define BN 128
#define BK 64
#define NTHREADS 256
#define A_TILE_BYTES (BM * 128)                      // 16384
#define B_TILE_BYTES (BN * 128)                      // 16384
#define STAGE_BYTES  (A_TILE_BYTES + B_TILE_BYTES)   // 32768
#define NSTAGE 3
#define SMEM_BYTES (NSTAGE * STAGE_BYTES)            // 98304

__device__ __forceinline__ void mma_f16(float* d, const uint32_t* a,
                                        uint32_t b0, uint32_t b1) {
    asm volatile(
        "mma.sync.aligned.m16n8k16.row.col.f32.f16.f16.f32 "
        "{%0,%1,%2,%3}, {%4,%5,%6,%7}, {%8,%9}, {%0,%1,%2,%3};"
        : "+f"(d[0]), "+f"(d[1]), "+f"(d[2]), "+f"(d[3])
        : "r"(a[0]), "r"(a[1]), "r"(a[2]), "r"(a[3]), "r"(b0), "r"(b1));
}

#define LDMATRIX_X4(r0, r1, r2, r3, addr)                                   \
    asm volatile("ldmatrix.sync.aligned.m8n8.x4.shared.b16 "                \
                 "{%0,%1,%2,%3}, [%4];"                                     \
                 : "=r"(r0), "=r"(r1), "=r"(r2), "=r"(r3) : "r"(addr))

__device__ __forceinline__ void cp_async16(uint32_t sm_dst, const void* g_src) {
    asm volatile("cp.async.cg.shared.global [%0], [%1], 16;"
                 :: "r"(sm_dst), "l"(g_src));
}

__global__ void __launch_bounds__(NTHREADS, 2)
arc_gemm_f16(const float* __restrict__ W, float* __restrict__ out,
             int C, int D, int ny)
{
    extern __shared__ char sm[];
    const uint32_t smaddr = (uint32_t)__cvta_generic_to_shared(sm);

    const int tid  = threadIdx.x;
    const int lane = tid & 31;
    const int warp = tid >> 5;
    const int y    = blockIdx.y;
    const int b0   = blockIdx.x * BM;
    const int c0   = y * BN;

    // ---- look-ahead W conversion: 16 rows of group y+LOOKAHEAD ----
    {
        int yt = y + LOOKAHEAD;
        if (yt < ny) {
            int rr = yt * BN + (int)blockIdx.x * 16 + (tid >> 4);
            int seg = tid & 15;
            if (rr < C) {
                const float4* src =
                    reinterpret_cast<const float4*>(W + (size_t)rr * (size_t)D);
                float4 v[8];
                #pragma unroll
                for (int q = 0; q < 8; q++) v[q] = src[seg + q * 16];
                float s = 0.0f;
                #pragma unroll
                for (int q = 0; q < 8; q++)
                    s += v[q].x * v[q].x + v[q].y * v[q].y
                       + v[q].z * v[q].z + v[q].w * v[q].w;
                #pragma unroll
                for (int off = 8; off > 0; off >>= 1)
                    s += __shfl_xor_sync(0xffffffffu, s, off);
                float rn = 1.0f / fmaxf(sqrtf(s), 1e-12f);
                uint2* dst = reinterpret_cast<uint2*>(g_Wh + (size_t)rr * (size_t)D);
                #pragma unroll
                for (int q = 0; q < 8; q++) {
                    __half2 h0 = __floats2half2_rn(v[q].x * rn, v[q].y * rn);
                    __half2 h1 = __floats2half2_rn(v[q].z * rn, v[q].w * rn);
                    uint2 u;
                    u.x = *reinterpret_cast<uint32_t*>(&h0);
                    u.y = *reinterpret_cast<uint32_t*>(&h1);
                    dst[seg + q * 16] = u;
                }
            }
            __syncthreads();
            if (tid == 0)
                asm volatile("red.release.gpu.global.add.u32 [%0], %1;"
                             :: "l"(&g_cnt[yt]), "r"(1u) : "memory");
        }
        if (y >= LOOKAHEAD) {
            if (tid == 0) {
                unsigned v = 0;
                do {
                    asm volatile("ld.acquire.gpu.global.u32 %0, [%1];"
                                 : "=r"(v) : "l"(&g_cnt[y]) : "memory");
                    if (v != 8u) __nanosleep(128);
                } while (v != 8u);
            }
            __syncthreads();
        }
    }

    // ---- GEMM body (round-6 config, unchanged) ----
    const int wm = (warp >> 2) * 64;   // 0, 64
    const int wn = (warp & 3) * 32;    // 0, 32, 64, 96
    const int r = lane >> 2;           // 0..7
    const int c = lane & 3;            // 0..3

    float acc[4][4][4];
    #pragma unroll
    for (int mi = 0; mi < 4; mi++)
        #pragma unroll
        for (int ni = 0; ni < 4; ni++)
            #pragma unroll
            for (int j = 0; j < 4; j++)
                acc[mi][ni][j] = 0.0f;

    const int nch = D / BK;   // 8
    const size_t rbytes = (size_t)D * 2;

    const int lane15 = lane & 15;
    const uint32_t kq16 = ((lane >> 4) & 1) << 4;
    const uint32_t sw = (uint32_t)(lane15 & 7) << 4;
    uint32_t relA[4], relB[2];
    #pragma unroll
    for (int t = 0; t < 4; t++)
        relA[t] = (uint32_t)(wm + t * 16 + lane15) * 128;
    #pragma unroll
    for (int t = 0; t < 2; t++)
        relB[t] = A_TILE_BYTES + (uint32_t)(wn + t * 16 + lane15) * 128;

    auto load_chunk = [&](int ch, int st) {
        uint32_t stage = smaddr + st * STAGE_BYTES;
        size_t koff = (size_t)ch * 128;
        #pragma unroll
        for (int h = 0; h < 8; h++) {
            int id = h * NTHREADS + tid;
            int row;
            uint32_t base;
            const char* gsrc;
            if (h < 4) {
                row = id >> 3;
                base = stage;
                gsrc = (const char*)g_Ah + (size_t)(b0 + row) * rbytes + koff;
            } else {
                int id2 = id - 1024;
                row = id2 >> 3;
                base = stage + A_TILE_BYTES;
                gsrc = (const char*)g_Wh + (size_t)(c0 + row) * rbytes + koff;
            }
            int seg = id & 7;
            uint32_t off = (uint32_t)row * 128 +
                           (((uint32_t)seg << 4) ^ (((uint32_t)row & 7) << 4));
            cp_async16(base + off, gsrc + seg * 16);
        }
        asm volatile("cp.async.commit_group;" ::: "memory");
    };

    load_chunk(0, 0);
    load_chunk(1, 1);

    for (int i = 0; i < nch; i++) {
        if (i + 1 < nch)
            asm volatile("cp.async.wait_group 1;" ::: "memory");
        else
            asm volatile("cp.async.wait_group 0;" ::: "memory");
        __syncthreads();

        if (i + 2 < nch)
            load_chunk(i + 2, (i + 2) % NSTAGE);

        uint32_t stage = smaddr + (i % NSTAGE) * STAGE_BYTES;

        #pragma unroll
        for (int ks = 0; ks < 4; ks++) {
            uint32_t kb = ((uint32_t)ks << 5) + kq16;
            uint32_t kx = kb ^ sw;

            uint32_t af[4][4];
            #pragma unroll
            for (int mt = 0; mt < 4; mt++)
                LDMATRIX_X4(af[mt][0], af[mt][1], af[mt][2], af[mt][3],
                            stage + relA[mt] + kx);

            uint32_t bf[2][4];
            #pragma unroll
            for (int nt = 0; nt < 2; nt++)
                LDMATRIX_X4(bf[nt][0], bf[nt][1], bf[nt][2], bf[nt][3],
                            stage + relB[nt] + kx);

            #pragma unroll
            for (int mt = 0; mt < 4; mt++)
                #pragma unroll
                for (int nt = 0; nt < 2; nt++) {
                    mma_f16(acc[mt][nt * 2 + 0], af[mt], bf[nt][0], bf[nt][2]);
                    mma_f16(acc[mt][nt * 2 + 1], af[mt], bf[nt][1], bf[nt][3]);
                }
        }
        __syncthreads();
    }

    // epilogue: bare stores (all scaling folded into operands)
    #pragma unroll
    for (int ni = 0; ni < 4; ni++) {
        int cc = c0 + wn + ni * 8 + 2 * c;
        if (cc < C) {
            #pragma unroll
            for (int mi = 0; mi < 4; mi++) {
                #pragma unroll
                for (int h = 0; h < 2; h++) {
                    int row = b0 + wm + mi * 16 + h * 8 + r;
                    float2 v = make_float2(acc[mi][ni][h * 2 + 0],
                                           acc[mi][ni][h * 2 + 1]);
                    *reinterpret_cast<float2*>(out + (size_t)row * (size_t)C + cc) = v;
                }
            }
        }
    }
}

// ---------------------------------------------------------------------------
// Fixup: margin at label columns only.
// ---------------------------------------------------------------------------
__global__ void fixup_kernel(const int* __restrict__ label, float* __restrict__ out,
                             int B, int C)
{
    int b = blockIdx.x * blockDim.x + threadIdx.x;
    if (b >= B) return;
    int c = label[b];
    if (c < 0 || c >= C) return;
    size_t idx = (size_t)b * (size_t)C + (size_t)c;
    float cosv = out[idx] * INV_S;
    float s2 = 1.0f - cosv * cosv;
    s2 = fminf(fmaxf(s2, 0.0f), 1.0f);
    float sine = sqrtf(s2);
    float phi = cosv * COS_M_C - sine * SIN_M_C;
    phi = (cosv > TH_C) ? phi : (cosv - MM_C);
    out[idx] = phi * S_SCALE;
}

// ---------------------------------------------------------------------------
// Launch
// ---------------------------------------------------------------------------
extern "C" void kernel_launch(void* const* d_in, const int* in_sizes, int n_in,
                              void* d_out, int out_size)
{
    const float* input  = (const float*)d_in[0];   // [B, D]
    const int*   label  = (const int*)  d_in[1];   // [B]
    const float* weight = (const float*)d_in[2];   // [C, D]
    float* out = (float*)d_out;                    // [B, C]

    const int B = in_sizes[1];
    const int D = in_sizes[0] / B;
    const int C = in_sizes[2] / D;
    const int ny = (C + BN - 1) / BN;

    cudaFuncSetAttribute(arc_gemm_f16, cudaFuncAttributeMaxDynamicSharedMemorySize,
                         SMEM_BYTES);

    __half* Ah;  cudaGetSymbolAddress((void**)&Ah, g_Ah);
    __half* Wh;  cudaGetSymbolAddress((void**)&Wh, g_Wh);

    // 0) reset arrive counters
    reset_flags_kernel<<<(ny + 255) / 256, 256>>>(ny);

    // 1) A prologue (all rows) + upfront W conversion for the first
    //    LOOKAHEAD groups only (the rest is converted inside the GEMM).
    norm_conv_kernel<<<B, 128>>>(input, Ah, S_SCALE, D);
    int upfront_rows = LOOKAHEAD * BN;
    if (upfront_rows > C) upfront_rows = C;
    norm_conv_kernel<<<upfront_rows, 128>>>(weight, Wh, 1.0f, D);

    // 2) GEMM with look-ahead W conversion (m-fast grid -> 8x L2 reuse)
    dim3 grid(B / BM, ny);
    arc_gemm_f16<<<grid, NTHREADS, SMEM_BYTES>>>(weight, out, C, D, ny);

    // 3) margin fixup at label columns
    fixup_kernel<<<(B + 127) / 128, 128>>>(label, out, B, C);
}

// round 10
// speedup vs baseline: 1.6466x; 1.0062x over previous
#include <cuda_runtime.h>
#include <cuda_fp16.h>
#include <math.h>
#include <stdint.h>

// ---------------------------------------------------------------------------
// ArcMarginProduct constants (S=30, M=0.5)
// ---------------------------------------------------------------------------
#define S_SCALE   30.0f
#define INV_S     (1.0f / 30.0f)
#define COS_M_C   0.87758256189037271612f   // cos(0.5)
#define SIN_M_C   0.47942553860420300027f   // sin(0.5)
#define TH_C     (-0.87758256189037271612f) // cos(pi - 0.5)
#define MM_C      7.19138307906304500405f   // S * sin(0.5) * 0.5

#define MAXB  1024
#define CPAD  100096     // 391 * 256; pad rows stay zero (zero-init statics)
#define DFIX  512
#define NYMAX 1024
#define LOOKAHEAD 64     // groups; > max groups resident per wave (37)

// fp16, normalization-folded operands
__device__ __align__(256) __half g_Ah[MAXB * DFIX];   // S * a / ||a||
__device__ __align__(256) __half g_Wh[CPAD * DFIX];   // w / ||w||
__device__ unsigned g_cnt[NYMAX];                     // per-group arrive counters

// ---------------------------------------------------------------------------
// Reset per-launch counters (deterministic graph replays).
// ---------------------------------------------------------------------------
__global__ void reset_flags_kernel(int n)
{
    int i = blockIdx.x * blockDim.x + threadIdx.x;
    if (i < n) g_cnt[i] = 0u;
}

// ---------------------------------------------------------------------------
// Prologue: per-row L2 norm -> scale -> fp16 convert -> scratch.
// Used for all of A and for the first LOOKAHEAD*BN rows of W.
// ---------------------------------------------------------------------------
__global__ void norm_conv_kernel(const float* __restrict__ x,
                                 __half* __restrict__ dst,
                                 float smul, int D)
{
    int row = blockIdx.x;
    const float4* xv = reinterpret_cast<const float4*>(x + (size_t)row * (size_t)D);
    float4 v = xv[threadIdx.x];

    float s = v.x * v.x + v.y * v.y + v.z * v.z + v.w * v.w;
    #pragma unroll
    for (int off = 16; off > 0; off >>= 1)
        s += __shfl_down_sync(0xffffffffu, s, off);

    __shared__ float wsum[4];
    __shared__ float s_sc;
    int lane = threadIdx.x & 31, wid = threadIdx.x >> 5;
    if (lane == 0) wsum[wid] = s;
    __syncthreads();
    if (threadIdx.x == 0) {
        float t = wsum[0] + wsum[1] + wsum[2] + wsum[3];
        s_sc = smul / fmaxf(sqrtf(t), 1e-12f);
    }
    __syncthreads();
    float sc = s_sc;

    __half2 h01 = __floats2half2_rn(v.x * sc, v.y * sc);
    __half2 h23 = __floats2half2_rn(v.z * sc, v.w * sc);
    __half2* p = reinterpret_cast<__half2*>(dst + (size_t)row * (size_t)D) + threadIdx.x * 2;
    p[0] = h01;
    p[1] = h23;
}

// ---------------------------------------------------------------------------
// fp16 tensor-core GEMM + look-ahead W conversion.
// GEMM: CTA 128x128, BK=64, 8 warps (2m x 4n), warp tile 64x32, 2 CTAs/SM,
//   SW128 XOR swizzle + ldmatrix, 3-stage cp.async pipeline.
// This round: strength-reduced loader (pure pointer increments) and
//   double-buffered B fragments (bf prefetch off the MMA critical path).
// ---------------------------------------------------------------------------
#define BM 128
#define BN 128
#define BK 64
#define NTHREADS 256
#define A_TILE_BYTES (BM * 128)                      // 16384
#define B_TILE_BYTES (BN * 128)                      // 16384
#define STAGE_BYTES  (A_TILE_BYTES + B_TILE_BYTES)   // 32768
#define NSTAGE 3
#define SMEM_BYTES (NSTAGE * STAGE_BYTES)            // 98304

__device__ __forceinline__ void mma_f16(float* d, const uint32_t* a,
                                        uint32_t b0, uint32_t b1) {
    asm volatile(
        "mma.sync.aligned.m16n8k16.row.col.f32.f16.f16.f32 "
        "{%0,%1,%2,%3}, {%4,%5,%6,%7}, {%8,%9}, {%0,%1,%2,%3};"
        : "+f"(d[0]), "+f"(d[1]), "+f"(d[2]), "+f"(d[3])
        : "r"(a[0]), "r"(a[1]), "r"(a[2]), "r"(a[3]), "r"(b0), "r"(b1));
}

#define LDMATRIX_X4(r0, r1, r2, r3, addr)                                   \
    asm volatile("ldmatrix.sync.aligned.m8n8.x4.shared.b16 "                \
                 "{%0,%1,%2,%3}, [%4];"                                     \
                 : "=r"(r0), "=r"(r1), "=r"(r2), "=r"(r3) : "r"(addr))

__device__ __forceinline__ void cp_async16(uint32_t sm_dst, const void* g_src) {
    asm volatile("cp.async.cg.shared.global [%0], [%1], 16;"
                 :: "r"(sm_dst), "l"(g_src));
}

__global__ void __launch_bounds__(NTHREADS, 2)
arc_gemm_f16(const float* __restrict__ W, float* __restrict__ out,
             int C, int D, int ny)
{
    extern __shared__ char sm[];
    const uint32_t smaddr = (uint32_t)__cvta_generic_to_shared(sm);

    const int tid  = threadIdx.x;
    const int lane = tid & 31;
    const int warp = tid >> 5;
    const int y    = blockIdx.y;
    const int b0   = blockIdx.x * BM;
    const int c0   = y * BN;

    // ---- look-ahead W conversion: 16 rows of group y+LOOKAHEAD ----
    {
        int yt = y + LOOKAHEAD;
        if (yt < ny) {
            int rr = yt * BN + (int)blockIdx.x * 16 + (tid >> 4);
            int seg = tid & 15;
            if (rr < C) {
                const float4* src =
                    reinterpret_cast<const float4*>(W + (size_t)rr * (size_t)D);
                float4 v[8];
                #pragma unroll
                for (int q = 0; q < 8; q++) v[q] = src[seg + q * 16];
                float s = 0.0f;
                #pragma unroll
                for (int q = 0; q < 8; q++)
                    s += v[q].x * v[q].x + v[q].y * v[q].y
                       + v[q].z * v[q].z + v[q].w * v[q].w;
                #pragma unroll
                for (int off = 8; off > 0; off >>= 1)
                    s += __shfl_xor_sync(0xffffffffu, s, off);
                float rn = 1.0f / fmaxf(sqrtf(s), 1e-12f);
                uint2* dst = reinterpret_cast<uint2*>(g_Wh + (size_t)rr * (size_t)D);
                #pragma unroll
                for (int q = 0; q < 8; q++) {
                    __half2 h0 = __floats2half2_rn(v[q].x * rn, v[q].y * rn);
                    __half2 h1 = __floats2half2_rn(v[q].z * rn, v[q].w * rn);
                    uint2 u;
                    u.x = *reinterpret_cast<uint32_t*>(&h0);
                    u.y = *reinterpret_cast<uint32_t*>(&h1);
                    dst[seg + q * 16] = u;
                }
            }
            __syncthreads();
            if (tid == 0)
                asm volatile("red.release.gpu.global.add.u32 [%0], %1;"
                             :: "l"(&g_cnt[yt]), "r"(1u) : "memory");
        }
        if (y >= LOOKAHEAD) {
            if (tid == 0) {
                unsigned v = 0;
                do {
                    asm volatile("ld.acquire.gpu.global.u32 %0, [%1];"
                                 : "=r"(v) : "l"(&g_cnt[y]) : "memory");
                    if (v != 8u) __nanosleep(128);
                } while (v != 8u);
            }
            __syncthreads();
        }
    }

    // ---- GEMM body ----
    const int wm = (warp >> 2) * 64;   // 0, 64
    const int wn = (warp & 3) * 32;    // 0, 32, 64, 96
    const int r = lane >> 2;           // 0..7
    const int c = lane & 3;            // 0..3

    float acc[4][4][4];
    #pragma unroll
    for (int mi = 0; mi < 4; mi++)
        #pragma unroll
        for (int ni = 0; ni < 4; ni++)
            #pragma unroll
            for (int j = 0; j < 4; j++)
                acc[mi][ni][j] = 0.0f;

    const int nch = D / BK;   // 8

    // --- strength-reduced loader state (all loop-invariant except +128/chunk) ---
    // per-thread: row0 = tid>>3 (0..31), seg = tid&7. Across the 4 h-steps of
    // each tile, row += 32 => row&7 constant => swizzle constant.
    const int rowL = tid >> 3;
    const int segL = tid & 7;
    const uint32_t swzL = (((uint32_t)segL << 4) ^ (((uint32_t)rowL & 7) << 4));
    const uint32_t smoffA = (uint32_t)rowL * 128 + swzL;
    const uint32_t smoffB = A_TILE_BYTES + smoffA;
    const char* gA = (const char*)g_Ah + (size_t)(b0 + rowL) * 1024 + segL * 16;
    const char* gB = (const char*)g_Wh + (size_t)(c0 + rowL) * 1024 + segL * 16;

    auto load_chunk = [&](int ch, int st) {
        uint32_t stage = smaddr + st * STAGE_BYTES;
        const char* ga = gA + ch * 128;
        uint32_t sa = stage + smoffA;
        #pragma unroll
        for (int h = 0; h < 4; h++) {
            cp_async16(sa, ga);
            sa += 32 * 128;        // +32 rows in smem
            ga += 32 * 1024;       // +32 rows in gmem
        }
        const char* gb = gB + ch * 128;
        uint32_t sb = stage + smoffB;
        #pragma unroll
        for (int h = 0; h < 4; h++) {
            cp_async16(sb, gb);
            sb += 32 * 128;
            gb += 32 * 1024;
        }
        asm volatile("cp.async.commit_group;" ::: "memory");
    };

    // ldmatrix per-thread addressing (SW128 swizzle)
    const int lane15 = lane & 15;
    const uint32_t kq16 = ((lane >> 4) & 1) << 4;
    const uint32_t sw = (uint32_t)(lane15 & 7) << 4;
    uint32_t relA[4], relB[2];
    #pragma unroll
    for (int t = 0; t < 4; t++)
        relA[t] = (uint32_t)(wm + t * 16 + lane15) * 128;
    #pragma unroll
    for (int t = 0; t < 2; t++)
        relB[t] = A_TILE_BYTES + (uint32_t)(wn + t * 16 + lane15) * 128;

    load_chunk(0, 0);
    load_chunk(1, 1);

    for (int i = 0; i < nch; i++) {
        if (i + 1 < nch)
            asm volatile("cp.async.wait_group 1;" ::: "memory");
        else
            asm volatile("cp.async.wait_group 0;" ::: "memory");
        __syncthreads();

        if (i + 2 < nch)
            load_chunk(i + 2, (i + 2) % NSTAGE);

        uint32_t stage = smaddr + (i % NSTAGE) * STAGE_BYTES;

        // B-fragment double buffer: prefetch bf(ks+1) before MMAs of ks.
        uint32_t bf[2][2][4];
        {
            uint32_t kx0 = kq16 ^ sw;
            #pragma unroll
            for (int nt = 0; nt < 2; nt++)
                LDMATRIX_X4(bf[0][nt][0], bf[0][nt][1], bf[0][nt][2], bf[0][nt][3],
                            stage + relB[nt] + kx0);
        }

        #pragma unroll
        for (int ks = 0; ks < 4; ks++) {
            const int cur = ks & 1, nxt = cur ^ 1;
            uint32_t kx = (((uint32_t)ks << 5) + kq16) ^ sw;

            uint32_t af[4][4];
            #pragma unroll
            for (int mt = 0; mt < 4; mt++)
                LDMATRIX_X4(af[mt][0], af[mt][1], af[mt][2], af[mt][3],
                            stage + relA[mt] + kx);

            if (ks < 3) {
                uint32_t kx2 = (((uint32_t)(ks + 1) << 5) + kq16) ^ sw;
                #pragma unroll
                for (int nt = 0; nt < 2; nt++)
                    LDMATRIX_X4(bf[nxt][nt][0], bf[nxt][nt][1],
                                bf[nxt][nt][2], bf[nxt][nt][3],
                                stage + relB[nt] + kx2);
            }

            #pragma unroll
            for (int mt = 0; mt < 4; mt++)
                #pragma unroll
                for (int nt = 0; nt < 2; nt++) {
                    mma_f16(acc[mt][nt * 2 + 0], af[mt], bf[cur][nt][0], bf[cur][nt][2]);
                    mma_f16(acc[mt][nt * 2 + 1], af[mt], bf[cur][nt][1], bf[cur][nt][3]);
                }
        }
        __syncthreads();
    }

    // epilogue: bare stores (all scaling folded into operands)
    #pragma unroll
    for (int ni = 0; ni < 4; ni++) {
        int cc = c0 + wn + ni * 8 + 2 * c;
        if (cc < C) {
            #pragma unroll
            for (int mi = 0; mi < 4; mi++) {
                #pragma unroll
                for (int h = 0; h < 2; h++) {
                    int row = b0 + wm + mi * 16 + h * 8 + r;
                    float2 v = make_float2(acc[mi][ni][h * 2 + 0],
                                           acc[mi][ni][h * 2 + 1]);
                    *reinterpret_cast<float2*>(out + (size_t)row * (size_t)C + cc) = v;
                }
            }
        }
    }
}

// ---------------------------------------------------------------------------
// Fixup: margin at label columns only.
// ---------------------------------------------------------------------------
__global__ void fixup_kernel(const int* __restrict__ label, float* __restrict__ out,
                             int B, int C)
{
    int b = blockIdx.x * blockDim.x + threadIdx.x;
    if (b >= B) return;
    int c = label[b];
    if (c < 0 || c >= C) return;
    size_t idx = (size_t)b * (size_t)C + (size_t)c;
    float cosv = out[idx] * INV_S;
    float s2 = 1.0f - cosv * cosv;
    s2 = fminf(fmaxf(s2, 0.0f), 1.0f);
    float sine = sqrtf(s2);
    float phi = cosv * COS_M_C - sine * SIN_M_C;
    phi = (cosv > TH_C) ? phi : (cosv - MM_C);
    out[idx] = phi * S_SCALE;
}

// ---------------------------------------------------------------------------
// Launch
// ---------------------------------------------------------------------------
extern "C" void kernel_launch(void* const* d_in, const int* in_sizes, int n_in,
                              void* d_out, int out_size)
{
    const float* input  = (const float*)d_in[0];   // [B, D]
    const int*   label  = (const int*)  d_in[1];   // [B]
    const float* weight = (const float*)d_in[2];   // [C, D]
    float* out = (float*)d_out;                    // [B, C]

    const int B = in_sizes[1];
    const int D = in_sizes[0] / B;
    const int C = in_sizes[2] / D;
    const int ny = (C + BN - 1) / BN;

    cudaFuncSetAttribute(arc_gemm_f16, cudaFuncAttributeMaxDynamicSharedMemorySize,
                         SMEM_BYTES);

    __half* Ah;  cudaGetSymbolAddress((void**)&Ah, g_Ah);
    __half* Wh;  cudaGetSymbolAddress((void**)&Wh, g_Wh);

    // 0) reset arrive counters
    reset_flags_kernel<<<(ny + 255) / 256, 256>>>(ny);

    // 1) A prologue (all rows) + upfront W conversion for the first
    //    LOOKAHEAD groups only (the rest is converted inside the GEMM).
    norm_conv_kernel<<<B, 128>>>(input, Ah, S_SCALE, D);
    int upfront_rows = LOOKAHEAD * BN;
    if (upfront_rows > C) upfront_rows = C;
    norm_conv_kernel<<<upfront_rows, 128>>>(weight, Wh, 1.0f, D);

    // 2) GEMM with look-ahead W conversion (m-fast grid -> 8x L2 reuse)
    dim3 grid(B / BM, ny);
    arc_gemm_f16<<<grid, NTHREADS, SMEM_BYTES>>>(weight, out, C, D, ny);

    // 3) margin fixup at label columns
    fixup_kernel<<<(B + 127) / 128, 128>>>(label, out, B, C);
}